// round 16
// baseline (speedup 1.0000x reference)
#include <cuda_runtime.h>
#include <math.h>
#include <stdint.h>

#define B_   128
#define I_   512
#define H_   512
#define SIXH 3072
#define BH   (B_*H_)          // 65536
#define BHH  (B_*H_*H_)       // 33554432
#define KSPLIT 4
#define KC   (I_/KSPLIT)      // 128

// ---------------- scratch (no allocations allowed) ----------------
__device__ float g_part[KSPLIT * B_ * SIXH]; // split-K partial gates

// packed f32x2 helpers (sm_103a FFMA2 path)
#define FMA2(c, a, b) \
    asm("fma.rn.f32x2 %0, %1, %2, %0;" : "+l"(c) : "l"(a), "l"(b))
#define PACK2(out, lo, hi) \
    asm("mov.b64 %0, {%1, %2};" : "=l"(out) : "f"(lo), "f"(hi))
#define UNPACK2(lo, hi, in) \
    asm("mov.b64 {%0, %1}, %2;" : "=f"(lo), "=f"(hi) : "l"(in))

// ---------------- K1: partial gates = x @ W^T  (split-K, FFMA2) --------------
// R11 proven config: 64x64 tile, BK=16, 256 threads, 4x4 FFMA2 register tile.
#define BM 64
#define BN 64
#define BK 16
__global__ void __launch_bounds__(256)
gemm_gates(const float* __restrict__ x, const float* __restrict__ W)
{
    __shared__ float As[BK][BM];
    __shared__ float Bs[BK][BN];

    const int m0 = blockIdx.y * BM;           // batch tile (2)
    const int n0 = blockIdx.x * BN;           // gate-col tile (48)
    const int kz = blockIdx.z;                // split-K slice (4)
    const int tid = threadIdx.x;              // 256 threads
    const int tx = tid & 15;
    const int ty = tid >> 4;

    unsigned long long acc2[4][2];
#pragma unroll
    for (int i = 0; i < 4; i++) { acc2[i][0] = 0ULL; acc2[i][1] = 0ULL; }

    const int lr = tid >> 2;    // 0..63 row within tile
    const int lq = tid & 3;     // 0..3  float4 within BK

    const int kbeg = kz * KC;
#pragma unroll 1
    for (int k0 = kbeg; k0 < kbeg + KC; k0 += BK) {
        float4 a = *(const float4*)(x + (m0 + lr) * I_ + k0 + lq * 4);
        As[lq*4+0][lr] = a.x; As[lq*4+1][lr] = a.y;
        As[lq*4+2][lr] = a.z; As[lq*4+3][lr] = a.w;
        float4 w = *(const float4*)(W + (n0 + lr) * I_ + k0 + lq * 4);
        Bs[lq*4+0][lr] = w.x; Bs[lq*4+1][lr] = w.y;
        Bs[lq*4+2][lr] = w.z; Bs[lq*4+3][lr] = w.w;
        __syncthreads();

#pragma unroll
        for (int kk = 0; kk < BK; kk++) {
            const float4 avv = *(const float4*)&As[kk][ty*4];
            const float4 bvv = *(const float4*)&Bs[kk][tx*4];
            unsigned long long b01, b23, ad;
            PACK2(b01, bvv.x, bvv.y);
            PACK2(b23, bvv.z, bvv.w);
            PACK2(ad, avv.x, avv.x);
            FMA2(acc2[0][0], ad, b01); FMA2(acc2[0][1], ad, b23);
            PACK2(ad, avv.y, avv.y);
            FMA2(acc2[1][0], ad, b01); FMA2(acc2[1][1], ad, b23);
            PACK2(ad, avv.z, avv.z);
            FMA2(acc2[2][0], ad, b01); FMA2(acc2[2][1], ad, b23);
            PACK2(ad, avv.w, avv.w);
            FMA2(acc2[3][0], ad, b01); FMA2(acc2[3][1], ad, b23);
        }
        __syncthreads();
    }

    float* dst = g_part + (size_t)kz * B_ * SIXH;
#pragma unroll
    for (int i = 0; i < 4; i++) {
        const int m = m0 + ty*4 + i;
        float4 r;
        UNPACK2(r.x, r.y, acc2[i][0]);
        UNPACK2(r.z, r.w, acc2[i][1]);
        *(float4*)(dst + m * SIXH + n0 + tx*4) = r;
    }
}

// ---------------- K2+K3 fused: gates -> state update + readout ---------------
// grid = B_ * 2 blocks (two half-row blocks per batch), 512 threads.
// Phase A (redundant per half-block): reduce split-K partials for this batch,
// compute f/s/o/q into smem + nq block-reduce. Phase B: stream 256 C rows.
#define PART 2
#define ROWS_PER_PART (H_ / PART)   // 256
__global__ void __launch_bounds__(512)
fused_state(const float* __restrict__ C_prev,
            const float* __restrict__ m_prev,
            const float* __restrict__ n_prev,
            const float* __restrict__ bias,
            float* __restrict__ out)
{
    __shared__ float qs[H_];
    __shared__ float fs[H_];
    __shared__ float ss[H_];
    __shared__ float os[H_];
    __shared__ float warp_s[16];
    __shared__ float denom_s;

    const int b = blockIdx.x >> 1;
    const int p = blockIdx.x & 1;
    const int h = threadIdx.x;           // 0..511
    const int warp = h >> 5;
    const int lane = h & 31;

    // ---- Phase A: gate transform for the whole batch ----
    float ig = bias[h];
    float fg = bias[H_   + h];
    float og = bias[2*H_ + h];
    float q  = bias[3*H_ + h];
    float k  = bias[4*H_ + h];
    float v  = bias[5*H_ + h];
#pragma unroll
    for (int kz = 0; kz < KSPLIT; kz++) {
        const float* g = g_part + (size_t)kz * B_ * SIXH + b * SIXH;
        ig += g[h];
        fg += g[H_   + h];
        og += g[2*H_ + h];
        q  += g[3*H_ + h];
        k  += g[4*H_ + h];
        v  += g[5*H_ + h];
    }

    const float inv_sqrt_h = 0.044194173824159216f; // 1/sqrt(512)
    const float mp = m_prev[b*H_ + h];
    const float m_t = fmaxf(fg + mp, ig);
    const float i_t = __expf(ig - m_t);
    const float f_t = __expf(fg + mp - m_t);
    const float k_t = k * inv_sqrt_h;
    const float n_t = f_t * n_prev[b*H_ + h] + i_t * k_t;

    qs[h] = q;
    fs[h] = f_t;
    ss[h] = i_t * v * k_t;
    os[h] = 1.f / (1.f + __expf(-og));

    const int idx = b*H_ + h;
    if (p == 0) {                        // write m_t / n_t once per batch
        out[BH + BHH + idx]      = m_t;
        out[BH + BHH + BH + idx] = n_t;
    }

    // nq[b] = sum_h n_t * q  (block reduction)
    float pr = n_t * q;
#pragma unroll
    for (int off = 16; off > 0; off >>= 1)
        pr += __shfl_down_sync(0xffffffff, pr, off);
    if (lane == 0) warp_s[warp] = pr;
    __syncthreads();
    if (h < 32) {
        float t = (h < 16) ? warp_s[h] : 0.f;
#pragma unroll
        for (int off = 8; off > 0; off >>= 1)
            t += __shfl_down_sync(0xffffffff, t, off);
        if (h == 0) denom_s = fmaxf(fabsf(t), 1e-6f);
    }
    __syncthreads();

    const float denom = denom_s;

    // ---- Phase B: stream this block's 256 C rows ----
    // 16 warps x 16 rows each
#pragma unroll 1
    for (int r = 0; r < ROWS_PER_PART / 16; r++) {
        const int i   = p * ROWS_PER_PART + warp * (ROWS_PER_PART / 16) + r;
        const int row = b * H_ + i;
        const float f = fs[i];
        const float s = ss[i];

        const float4* Cin  = (const float4*)(C_prev + (size_t)row * H_);
        float4*       Cout = (float4*)(out + BH + (size_t)row * H_);

        float acc = 0.f;
#pragma unroll
        for (int t = 0; t < 4; t++) {
            const int j4 = lane + t * 32;
            float4 c = __ldcs(Cin + j4);
            c.x = fmaf(f, c.x, s);
            c.y = fmaf(f, c.y, s);
            c.z = fmaf(f, c.z, s);
            c.w = fmaf(f, c.w, s);
            __stcs(Cout + j4, c);
            const int j = j4 * 4;
            acc = fmaf(c.x, qs[j],   acc);
            acc = fmaf(c.y, qs[j+1], acc);
            acc = fmaf(c.z, qs[j+2], acc);
            acc = fmaf(c.w, qs[j+3], acc);
        }
#pragma unroll
        for (int off = 16; off > 0; off >>= 1)
            acc += __shfl_down_sync(0xffffffff, acc, off);

        if (lane == 0)
            out[row] = os[i] * (acc / denom);   // h_t
    }
}

// ---------------- launch ------------------------------------------------------
extern "C" void kernel_launch(void* const* d_in, const int* in_sizes, int n_in,
                              void* d_out, int out_size)
{
    const float* x      = (const float*)d_in[0];
    // d_in[1] = h_prev (unused by the reference math)
    const float* C_prev = (const float*)d_in[2];
    const float* m_prev = (const float*)d_in[3];
    const float* n_prev = (const float*)d_in[4];
    const float* W      = (const float*)d_in[5];
    const float* bias   = (const float*)d_in[6];
    float* out = (float*)d_out;

    dim3 g1(SIXH / BN, B_ / BM, KSPLIT);          // 48 x 2 x 4 = 384 blocks
    gemm_gates<<<g1, 256>>>(x, W);
    fused_state<<<B_ * PART, 512>>>(C_prev, m_prev, n_prev, bias, out);
}